// round 7
// baseline (speedup 1.0000x reference)
#include <cuda_runtime.h>
#include <cuda_fp16.h>
#include <math.h>

#define BB 8
#define TT 2048
#define EE 1024
#define HH 128
#define BT (BB*TT)

// ---------------- scratch (device globals: allocation-free) ----------------
__device__ float g_k[BT*HH];
__device__ float g_q[BT*HH];
__device__ float g_v[BT*HH];
__device__ float g_S[(size_t)BB*TT*TT];                 // fp32 scores
__device__ __align__(256) __half g_E[(size_t)BB*TT*TT]; // exp(S-cmax) fp16
__device__ float g_psum[8*BT];
__device__ unsigned g_cmaxu[BT];          // encoded column max
__device__ float g_crcp[BT];              // 1/den

// ---------------- helpers --------------------------------------------------
__device__ __forceinline__ float tf32_rna(float x) {
    unsigned u;
    asm("cvt.rna.tf32.f32 %0, %1;" : "=r"(u) : "f"(x));
    return __uint_as_float(u);
}
__device__ __forceinline__ unsigned fau(float x) { return __float_as_uint(x); }

// monotone float<->unsigned encoding for atomicMax
__device__ __forceinline__ unsigned fenc(float f) {
    unsigned u = __float_as_uint(f);
    return (u & 0x80000000u) ? ~u : (u | 0x80000000u);
}
__device__ __forceinline__ float fdec(unsigned e) {
    unsigned u = (e & 0x80000000u) ? (e & 0x7fffffffu) : ~e;
    return __uint_as_float(u);
}

__device__ __forceinline__ void mma8(float c[4], const unsigned a[4], const unsigned b[2]) {
    asm volatile(
        "mma.sync.aligned.m16n8k8.row.col.f32.tf32.tf32.f32 "
        "{%0,%1,%2,%3}, {%4,%5,%6,%7}, {%8,%9}, {%0,%1,%2,%3};\n"
        : "+f"(c[0]), "+f"(c[1]), "+f"(c[2]), "+f"(c[3])
        : "r"(a[0]), "r"(a[1]), "r"(a[2]), "r"(a[3]), "r"(b[0]), "r"(b[1]));
}
__device__ __forceinline__ void mma16h(float c[4], const unsigned a[4], const unsigned b[2]) {
    asm volatile(
        "mma.sync.aligned.m16n8k16.row.col.f32.f16.f16.f32 "
        "{%0,%1,%2,%3}, {%4,%5,%6,%7}, {%8,%9}, {%0,%1,%2,%3};\n"
        : "+f"(c[0]), "+f"(c[1]), "+f"(c[2]), "+f"(c[3])
        : "r"(a[0]), "r"(a[1]), "r"(a[2]), "r"(a[3]), "r"(b[0]), "r"(b[1]));
}
__device__ __forceinline__ void ldsm_x4(unsigned r[4], unsigned addr) {
    asm volatile("ldmatrix.sync.aligned.m8n8.x4.shared.b16 {%0,%1,%2,%3}, [%4];"
                 : "=r"(r[0]), "=r"(r[1]), "=r"(r[2]), "=r"(r[3]) : "r"(addr));
}
__device__ __forceinline__ void ldsm_x2t(unsigned r[2], unsigned addr) {
    asm volatile("ldmatrix.sync.aligned.m8n8.x2.trans.shared.b16 {%0,%1}, [%2];"
                 : "=r"(r[0]), "=r"(r[1]) : "r"(addr));
}
__device__ __forceinline__ float ex2f(float y) {
    float e;
    asm("ex2.approx.f32 %0, %1;" : "=f"(e) : "f"(y));
    return e;
}
__device__ __forceinline__ float4 cvt4(float4 v) {
    return make_float4(tf32_rna(v.x), tf32_rna(v.y), tf32_rna(v.z), tf32_rna(v.w));
}
__device__ __forceinline__ float4 sub4(float4 a, float4 b) {
    return make_float4(a.x - b.x, a.y - b.y, a.z - b.z, a.w - b.w);
}

// ---------------- init: cmax accumulators to encoded -inf ------------------
__global__ void init_cmax() {
    g_cmaxu[blockIdx.x * 256 + threadIdx.x] = 0x007fffffu;  // fenc(-inf)
}

// ---------------- K1: q/k/v = x @ W  (3xTF32, 2-stage pipeline) ------------
__global__ void __launch_bounds__(256) qkv_kernel(const float* __restrict__ x,
                                                  const float* __restrict__ Wk,
                                                  const float* __restrict__ Wq,
                                                  const float* __restrict__ Wv) {
    const float* W    = (blockIdx.y == 0) ? Wk : (blockIdx.y == 1) ? Wq : Wv;
    float*       outp = (blockIdx.y == 0) ? g_k : (blockIdx.y == 1) ? g_q : g_v;

    __shared__ float Ah[2][128][12], Al[2][128][12];   // x big/small  [m][k8]
    __shared__ float Bh[2][8][136],  Bl[2][8][136];    // W big/small  [k8][n]

    int tid = threadIdx.x;
    int m0 = blockIdx.x * 128;
    int warp = tid >> 5, lane = tid & 31, g = lane >> 2, tq = lane & 3;
    int mbase = (warp >> 1) * 32, nbase = (warp & 1) * 64;
    int ra = tid >> 1, ca = (tid & 1) * 4;
    int rb = tid >> 5, cb = (tid & 31) * 4;

    float acc[2][8][4];
#pragma unroll
    for (int i = 0; i < 2; i++)
#pragma unroll
        for (int j = 0; j < 8; j++)
#pragma unroll
            for (int q = 0; q < 4; q++) acc[i][j][q] = 0.f;

    float4 sA, sB;
    auto LOAD = [&](int k0) {
        sA = *(const float4*)&x[(size_t)(m0 + ra) * EE + k0 + ca];
        sB = *(const float4*)&W[(size_t)(k0 + rb) * HH + cb];
    };
    auto STORE = [&](int bsel) {
        float4 h = cvt4(sA);
        *(float4*)&Ah[bsel][ra][ca] = h;
        *(float4*)&Al[bsel][ra][ca] = sub4(sA, h);
        float4 hb = cvt4(sB);
        *(float4*)&Bh[bsel][rb][cb] = hb;
        *(float4*)&Bl[bsel][rb][cb] = sub4(sB, hb);
    };
    auto COMPUTE = [&](int bsel) {
        unsigned ah[2][4], al[2][4];
#pragma unroll
        for (int ma = 0; ma < 2; ma++) {
            int r0 = mbase + ma * 16 + g;
            ah[ma][0] = fau(Ah[bsel][r0][tq]);     ah[ma][1] = fau(Ah[bsel][r0 + 8][tq]);
            ah[ma][2] = fau(Ah[bsel][r0][tq + 4]); ah[ma][3] = fau(Ah[bsel][r0 + 8][tq + 4]);
            al[ma][0] = fau(Al[bsel][r0][tq]);     al[ma][1] = fau(Al[bsel][r0 + 8][tq]);
            al[ma][2] = fau(Al[bsel][r0][tq + 4]); al[ma][3] = fau(Al[bsel][r0 + 8][tq + 4]);
        }
#pragma unroll
        for (int nb = 0; nb < 8; nb++) {
            int cc = nbase + nb * 8 + g;
            unsigned bh[2], bl[2];
            bh[0] = fau(Bh[bsel][tq][cc]); bh[1] = fau(Bh[bsel][tq + 4][cc]);
            bl[0] = fau(Bl[bsel][tq][cc]); bl[1] = fau(Bl[bsel][tq + 4][cc]);
#pragma unroll
            for (int ma = 0; ma < 2; ma++) {
                mma8(acc[ma][nb], ah[ma], bh);
                mma8(acc[ma][nb], ah[ma], bl);
                mma8(acc[ma][nb], al[ma], bh);
            }
        }
    };

    LOAD(0); STORE(0); __syncthreads();
    const int NC = EE / 8;
    for (int c = 0; c < NC; c++) {
        if (c + 1 < NC) LOAD((c + 1) * 8);
        COMPUTE(c & 1);
        if (c + 1 < NC) STORE((c + 1) & 1);
        __syncthreads();
    }

#pragma unroll
    for (int ma = 0; ma < 2; ma++)
#pragma unroll
        for (int nb = 0; nb < 8; nb++) {
            int r0 = m0 + mbase + ma * 16 + g;
            int cc = nbase + nb * 8 + 2 * tq;
            *(float2*)&outp[(size_t)r0 * HH + cc]       = make_float2(acc[ma][nb][0], acc[ma][nb][1]);
            *(float2*)&outp[(size_t)(r0 + 8) * HH + cc] = make_float2(acc[ma][nb][2], acc[ma][nb][3]);
        }
}

// ---------------- K2: S = sqrt(H)*q@k^T + fused column max -----------------
__global__ void __launch_bounds__(256) score_kernel() {
    int bx = blockIdx.x, by = blockIdx.y;
    if (bx < by) return;                      // tile fully above diagonal
    int t0 = bx * 128, s0 = by * 128, b = blockIdx.z;

    __shared__ float Ah[2][128][12], Al[2][128][12];   // q  [t][h8]
    __shared__ float Bh[2][8][136],  Bl[2][8][136];    // k^T [h8][s]

    const float* qb = g_q + (size_t)b * TT * HH;
    const float* kb = g_k + (size_t)b * TT * HH;

    int tid = threadIdx.x;
    int warp = tid >> 5, lane = tid & 31, g = lane >> 2, tq = lane & 3;
    int mbase = (warp >> 1) * 32, nbase = (warp & 1) * 64;
    int ra = tid >> 1, ca = (tid & 1) * 4;

    float acc[2][8][4];
#pragma unroll
    for (int i = 0; i < 2; i++)
#pragma unroll
        for (int j = 0; j < 8; j++)
#pragma unroll
            for (int q = 0; q < 4; q++) acc[i][j][q] = 0.f;

    float4 sA, sB;
    auto LOAD = [&](int h0) {
        sA = *(const float4*)&qb[(size_t)(t0 + ra) * HH + h0 + ca];
        sB = *(const float4*)&kb[(size_t)(s0 + ra) * HH + h0 + ca];
    };
    auto STORE = [&](int bsel) {
        float4 h = cvt4(sA);
        *(float4*)&Ah[bsel][ra][ca] = h;
        *(float4*)&Al[bsel][ra][ca] = sub4(sA, h);
        float vv[4] = {sB.x, sB.y, sB.z, sB.w};
#pragma unroll
        for (int j = 0; j < 4; j++) {
            float hb = tf32_rna(vv[j]);
            Bh[bsel][ca + j][ra] = hb;
            Bl[bsel][ca + j][ra] = vv[j] - hb;
        }
    };
    auto COMPUTE = [&](int bsel) {
        unsigned ah[2][4], al[2][4];
#pragma unroll
        for (int ma = 0; ma < 2; ma++) {
            int r0 = mbase + ma * 16 + g;
            ah[ma][0] = fau(Ah[bsel][r0][tq]);     ah[ma][1] = fau(Ah[bsel][r0 + 8][tq]);
            ah[ma][2] = fau(Ah[bsel][r0][tq + 4]); ah[ma][3] = fau(Ah[bsel][r0 + 8][tq + 4]);
            al[ma][0] = fau(Al[bsel][r0][tq]);     al[ma][1] = fau(Al[bsel][r0 + 8][tq]);
            al[ma][2] = fau(Al[bsel][r0][tq + 4]); al[ma][3] = fau(Al[bsel][r0 + 8][tq + 4]);
        }
#pragma unroll
        for (int nb = 0; nb < 8; nb++) {
            int cc = nbase + nb * 8 + g;
            unsigned bh[2], bl[2];
            bh[0] = fau(Bh[bsel][tq][cc]); bh[1] = fau(Bh[bsel][tq + 4][cc]);
            bl[0] = fau(Bl[bsel][tq][cc]); bl[1] = fau(Bl[bsel][tq + 4][cc]);
#pragma unroll
            for (int ma = 0; ma < 2; ma++) {
                mma8(acc[ma][nb], ah[ma], bh);
                mma8(acc[ma][nb], ah[ma], bl);
                mma8(acc[ma][nb], al[ma], bh);
            }
        }
    };

    LOAD(0); STORE(0); __syncthreads();
    const int NC = HH / 8;
    for (int c = 0; c < NC; c++) {
        if (c + 1 < NC) LOAD((c + 1) * 8);
        COMPUTE(c & 1);
        if (c + 1 < NC) STORE((c + 1) & 1);
        __syncthreads();
    }

    float* Sb = g_S + (size_t)b * TT * TT;
    const float scale = 11.31370849898476f;   // sqrt(128)
#pragma unroll
    for (int ma = 0; ma < 2; ma++)
#pragma unroll
        for (int nb = 0; nb < 8; nb++) {
            int r0 = t0 + mbase + ma * 16 + g;
            int cc = s0 + nbase + nb * 8 + 2 * tq;
            *(float2*)&Sb[(size_t)r0 * TT + cc] =
                make_float2(acc[ma][nb][0] * scale, acc[ma][nb][1] * scale);
            *(float2*)&Sb[(size_t)(r0 + 8) * TT + cc] =
                make_float2(acc[ma][nb][2] * scale, acc[ma][nb][3] * scale);
        }

    // fused per-column max (valid region only on the diagonal tile)
    bool diag = (bx == by);
#pragma unroll
    for (int nb = 0; nb < 8; nb++) {
#pragma unroll
        for (int p = 0; p < 2; p++) {
            int scol = nbase + nb * 8 + 2 * tq + p;   // local col in tile
            float m = -INFINITY;
#pragma unroll
            for (int ma = 0; ma < 2; ma++) {
#pragma unroll
                for (int rp = 0; rp < 2; rp++) {
                    int rrow = mbase + ma * 16 + g + rp * 8;
                    float v = acc[ma][nb][rp * 2 + p] * scale;
                    if (!diag || rrow >= scol) m = fmaxf(m, v);
                }
            }
            m = fmaxf(m, __shfl_xor_sync(0xffffffffu, m, 4));
            m = fmaxf(m, __shfl_xor_sync(0xffffffffu, m, 8));
            m = fmaxf(m, __shfl_xor_sync(0xffffffffu, m, 16));
            if (g == 0)
                atomicMax(&g_cmaxu[(size_t)b * TT + s0 + scol], fenc(m));
        }
    }
}

// -------- pass B: E = exp(S - cmax) -> fp16, partial column sums -----------
__global__ void expsum_partial() {
    int col = blockIdx.x * 256 + threadIdx.x;
    int b = col >> 11, s = col & 2047;
    int t0c = blockIdx.y * 256, t1c = t0c + 256;
    const float* Sb = g_S + (size_t)b * TT * TT;
    __half* Eb = g_E + (size_t)b * TT * TT;
    const float L = 1.4426950408889634f;
    float cml = fdec(g_cmaxu[col]) * L;

    // zero the garbage region above the diagonal inside this column's 128-block
    int z0 = s & ~127; if (z0 < t0c) z0 = t0c;
    int z1 = (s < t1c) ? s : t1c;
    for (int t = z0; t < z1; t++) Eb[(size_t)t * TT + s] = __float2half(0.f);

    float d0 = 0.f, d1 = 0.f;
    int t = (s > t0c) ? s : t0c;
    for (; t + 1 < t1c; t += 2) {
        float v0 = Sb[(size_t)t * TT + s];
        float v1 = Sb[(size_t)(t + 1) * TT + s];
        float e0 = ex2f(fmaf(v0, L, -cml));
        float e1 = ex2f(fmaf(v1, L, -cml));
        Eb[(size_t)t * TT + s]       = __float2half(e0);
        Eb[(size_t)(t + 1) * TT + s] = __float2half(e1);
        d0 += e0; d1 += e1;
    }
    for (; t < t1c; t++) {
        float e = ex2f(fmaf(Sb[(size_t)t * TT + s], L, -cml));
        Eb[(size_t)t * TT + s] = __float2half(e);
        d0 += e;
    }
    g_psum[blockIdx.y * BT + col] = d0 + d1;
}

__global__ void den_combine() {
    int col = blockIdx.x * 256 + threadIdx.x;
    float d = 0.f;
#pragma unroll
    for (int c = 0; c < 8; c++) d += g_psum[c * BT + col];
    g_crcp[col] = 1.f / d;
}

// ---------------- K4: out = E @ (v*crcp)  (fp16 mma, pipelined) ------------
// block 256, tile 128(t) x 128(H), s-chunk 16, double-buffered
__global__ void __launch_bounds__(256) out_kernel(float* __restrict__ outp) {
    int t0 = blockIdx.x * 128;
    int b  = blockIdx.y;

    __shared__ __half As[2][128][24];    // E tile  [t][s16]  (48B rows)
    __shared__ __half Bs[2][16][136];    // v' tile [s16][h]  (272B rows)

    const __half* Eb = g_E + (size_t)b * TT * TT;
    const float* vb = g_v + (size_t)b * TT * HH;
    const float* crcp = g_crcp + b * TT;

    int tid = threadIdx.x;
    int warp = tid >> 5, lane = tid & 31, g = lane >> 2, tq = lane & 3;
    int mbase = (warp >> 1) * 32, nbase = (warp & 1) * 64;
    int ra = tid >> 1, caa = (tid & 1) * 8;   // A stage: 128 rows x 16 halves
    int rb = tid >> 4, cbb = (tid & 15) * 8;  // B stage: 16 rows x 128 halves

    float acc[2][8][4];
#pragma unroll
    for (int i = 0; i < 2; i++)
#pragma unroll
        for (int j = 0; j < 8; j++)
#pragma unroll
            for (int q = 0; q < 4; q++) acc[i][j][q] = 0.f;

    uint4 sA; float4 sB0, sB1; float sC;
    auto LOAD = [&](int s0c) {
        sA = *(const uint4*)&Eb[(size_t)(t0 + ra) * TT + s0c + caa];
        sB0 = *(const float4*)&vb[(size_t)(s0c + rb) * HH + cbb];
        sB1 = *(const float4*)&vb[(size_t)(s0c + rb) * HH + cbb + 4];
        sC = crcp[s0c + rb];
    };
    auto STORE = [&](int bsel) {
        *(uint4*)&As[bsel][ra][caa] = sA;
        __half2 h0 = __floats2half2_rn(sB0.x * sC, sB0.y * sC);
        __half2 h1 = __floats2half2_rn(sB0.z * sC, sB0.w * sC);
        __half2 h2 = __floats2half2_rn(sB1.x * sC, sB1.y * sC);
        __half2 h3 = __floats2half2_rn(sB1.z * sC, sB1.w * sC);
        uint4 u;
        u.x = *reinterpret_cast<unsigned*>(&h0);
        u.y = *reinterpret_cast<unsigned*>(&h1);
        u.z = *reinterpret_cast<unsigned*>(&h2);
        u.w = *reinterpret_cast<unsigned*>(&h3);
        *(uint4*)&Bs[bsel][rb][cbb] = u;
    };
    auto COMPUTE = [&](int bsel) {
        unsigned a[2][4];
#pragma unroll
        for (int ma = 0; ma < 2; ma++) {
            int r = mbase + ma * 16 + (lane & 7) + ((lane >> 3) & 1) * 8;
            int c = ((lane >> 4) & 1) * 8;
            unsigned ad = (unsigned)__cvta_generic_to_shared(&As[bsel][r][c]);
            ldsm_x4(a[ma], ad);
        }
#pragma unroll
        for (int nb = 0; nb < 8; nb++) {
            int cc = nbase + nb * 8;
            unsigned bfr[2];
            unsigned bd = (unsigned)__cvta_generic_to_shared(&Bs[bsel][lane & 15][cc]);
            ldsm_x2t(bfr, bd);
            mma16h(acc[0][nb], a[0], bfr);
            mma16h(acc[1][nb], a[1], bfr);
        }
    };

    LOAD(0); STORE(0); __syncthreads();
    const int NC = t0 / 16 + 8;          // s <= t0+127
    for (int c = 0; c < NC; c++) {
        if (c + 1 < NC) LOAD((c + 1) * 16);
        COMPUTE(c & 1);
        if (c + 1 < NC) STORE((c + 1) & 1);
        __syncthreads();
    }

#pragma unroll
    for (int ma = 0; ma < 2; ma++)
#pragma unroll
        for (int nb = 0; nb < 8; nb++) {
            int r0 = t0 + mbase + ma * 16 + g;
            int cc = nbase + nb * 8 + 2 * tq;
            *(float2*)&outp[((size_t)b * TT + r0) * HH + cc] =
                make_float2(acc[ma][nb][0], acc[ma][nb][1]);
            *(float2*)&outp[((size_t)b * TT + r0 + 8) * HH + cc] =
                make_float2(acc[ma][nb][2], acc[ma][nb][3]);
        }
}

// ---------------------------------------------------------------------------
extern "C" void kernel_launch(void* const* d_in, const int* in_sizes, int n_in,
                              void* d_out, int out_size) {
    const float* x  = (const float*)d_in[0];
    const float* Wk = (const float*)d_in[1];
    const float* Wq = (const float*)d_in[2];
    const float* Wv = (const float*)d_in[3];
    float* out = (float*)d_out;

    init_cmax<<<BT / 256, 256>>>();
    qkv_kernel<<<dim3(BT / 128, 3), 256>>>(x, Wk, Wq, Wv);
    score_kernel<<<dim3(TT / 128, TT / 128, BB), 256>>>();
    expsum_partial<<<dim3(BT / 256, 8), 256>>>();
    den_combine<<<BT / 256, 256>>>();
    out_kernel<<<dim3(TT / 128, BB), 256>>>(out);
}

// round 9
// speedup vs baseline: 1.2484x; 1.2484x over previous
#include <cuda_runtime.h>
#include <math.h>

#define BB 8
#define TT 2048
#define EE 1024
#define HH 128
#define BT (BB*TT)

// ---------------- scratch (device globals: allocation-free) ----------------
__device__ float g_k[BT*HH];
__device__ float g_q[BT*HH];
__device__ float g_v[BT*HH];
__device__ float g_S[(size_t)BB*TT*TT];   // S, then overwritten with E=exp(S-cmax)
__device__ float g_psum[8*BT];
__device__ unsigned g_cmaxu[BT];          // encoded column max (atomicMax)
__device__ float g_crcp[BT];              // 1/den

// ---------------- helpers --------------------------------------------------
__device__ __forceinline__ float tf32_rna(float x) {
    unsigned u;
    asm("cvt.rna.tf32.f32 %0, %1;" : "=r"(u) : "f"(x));
    return __uint_as_float(u);
}
__device__ __forceinline__ unsigned fau(float x) { return __float_as_uint(x); }

// monotone float<->unsigned encoding for atomicMax
__device__ __forceinline__ unsigned fenc(float f) {
    unsigned u = __float_as_uint(f);
    return (u & 0x80000000u) ? ~u : (u | 0x80000000u);
}
__device__ __forceinline__ float fdec(unsigned e) {
    unsigned u = (e & 0x80000000u) ? (e & 0x7fffffffu) : ~e;
    return __uint_as_float(u);
}

__device__ __forceinline__ void mma8(float c[4], const unsigned a[4], const unsigned b[2]) {
    asm volatile(
        "mma.sync.aligned.m16n8k8.row.col.f32.tf32.tf32.f32 "
        "{%0,%1,%2,%3}, {%4,%5,%6,%7}, {%8,%9}, {%0,%1,%2,%3};\n"
        : "+f"(c[0]), "+f"(c[1]), "+f"(c[2]), "+f"(c[3])
        : "r"(a[0]), "r"(a[1]), "r"(a[2]), "r"(a[3]), "r"(b[0]), "r"(b[1]));
}
__device__ __forceinline__ float ex2f(float y) {
    float e;
    asm("ex2.approx.f32 %0, %1;" : "=f"(e) : "f"(y));
    return e;
}
__device__ __forceinline__ float4 cvt4(float4 v) {
    return make_float4(tf32_rna(v.x), tf32_rna(v.y), tf32_rna(v.z), tf32_rna(v.w));
}
__device__ __forceinline__ float4 sub4(float4 a, float4 b) {
    return make_float4(a.x - b.x, a.y - b.y, a.z - b.z, a.w - b.w);
}

// ---------------- init: cmax accumulators to encoded -inf ------------------
__global__ void init_cmax() {
    g_cmaxu[blockIdx.x * 256 + threadIdx.x] = 0x007fffffu;  // fenc(-inf)
}

// ---------------- K1: q/k/v = x @ W  (3xTF32, 2-stage pipeline) ------------
__global__ void __launch_bounds__(256) qkv_kernel(const float* __restrict__ x,
                                                  const float* __restrict__ Wk,
                                                  const float* __restrict__ Wq,
                                                  const float* __restrict__ Wv) {
    const float* W    = (blockIdx.y == 0) ? Wk : (blockIdx.y == 1) ? Wq : Wv;
    float*       outp = (blockIdx.y == 0) ? g_k : (blockIdx.y == 1) ? g_q : g_v;

    __shared__ float Ah[2][128][12], Al[2][128][12];   // x big/small  [m][k8]
    __shared__ float Bh[2][8][136],  Bl[2][8][136];    // W big/small  [k8][n]

    int tid = threadIdx.x;
    int m0 = blockIdx.x * 128;
    int warp = tid >> 5, lane = tid & 31, g = lane >> 2, tq = lane & 3;
    int mbase = (warp >> 1) * 32, nbase = (warp & 1) * 64;
    int ra = tid >> 1, ca = (tid & 1) * 4;
    int rb = tid >> 5, cb = (tid & 31) * 4;

    float acc[2][8][4];
#pragma unroll
    for (int i = 0; i < 2; i++)
#pragma unroll
        for (int j = 0; j < 8; j++)
#pragma unroll
            for (int q = 0; q < 4; q++) acc[i][j][q] = 0.f;

    float4 sA, sB;
    auto LOAD = [&](int k0) {
        sA = *(const float4*)&x[(size_t)(m0 + ra) * EE + k0 + ca];
        sB = *(const float4*)&W[(size_t)(k0 + rb) * HH + cb];
    };
    auto STORE = [&](int bsel) {
        float4 h = cvt4(sA);
        *(float4*)&Ah[bsel][ra][ca] = h;
        *(float4*)&Al[bsel][ra][ca] = sub4(sA, h);
        float4 hb = cvt4(sB);
        *(float4*)&Bh[bsel][rb][cb] = hb;
        *(float4*)&Bl[bsel][rb][cb] = sub4(sB, hb);
    };
    auto COMPUTE = [&](int bsel) {
        unsigned ah[2][4], al[2][4];
#pragma unroll
        for (int ma = 0; ma < 2; ma++) {
            int r0 = mbase + ma * 16 + g;
            ah[ma][0] = fau(Ah[bsel][r0][tq]);     ah[ma][1] = fau(Ah[bsel][r0 + 8][tq]);
            ah[ma][2] = fau(Ah[bsel][r0][tq + 4]); ah[ma][3] = fau(Ah[bsel][r0 + 8][tq + 4]);
            al[ma][0] = fau(Al[bsel][r0][tq]);     al[ma][1] = fau(Al[bsel][r0 + 8][tq]);
            al[ma][2] = fau(Al[bsel][r0][tq + 4]); al[ma][3] = fau(Al[bsel][r0 + 8][tq + 4]);
        }
#pragma unroll
        for (int nb = 0; nb < 8; nb++) {
            int cc = nbase + nb * 8 + g;
            unsigned bh[2], bl[2];
            bh[0] = fau(Bh[bsel][tq][cc]); bh[1] = fau(Bh[bsel][tq + 4][cc]);
            bl[0] = fau(Bl[bsel][tq][cc]); bl[1] = fau(Bl[bsel][tq + 4][cc]);
#pragma unroll
            for (int ma = 0; ma < 2; ma++) {
                mma8(acc[ma][nb], ah[ma], bh);
                mma8(acc[ma][nb], ah[ma], bl);
                mma8(acc[ma][nb], al[ma], bh);
            }
        }
    };

    LOAD(0); STORE(0); __syncthreads();
    const int NC = EE / 8;
    for (int c = 0; c < NC; c++) {
        if (c + 1 < NC) LOAD((c + 1) * 8);
        COMPUTE(c & 1);
        if (c + 1 < NC) STORE((c + 1) & 1);
        __syncthreads();
    }

#pragma unroll
    for (int ma = 0; ma < 2; ma++)
#pragma unroll
        for (int nb = 0; nb < 8; nb++) {
            int r0 = m0 + mbase + ma * 16 + g;
            int cc = nbase + nb * 8 + 2 * tq;
            *(float2*)&outp[(size_t)r0 * HH + cc]       = make_float2(acc[ma][nb][0], acc[ma][nb][1]);
            *(float2*)&outp[(size_t)(r0 + 8) * HH + cc] = make_float2(acc[ma][nb][2], acc[ma][nb][3]);
        }
}

// ---------------- K2: S = sqrt(H)*q@k^T + fused column max -----------------
__global__ void __launch_bounds__(256) score_kernel() {
    int bx = blockIdx.x, by = blockIdx.y;
    if (bx < by) return;                      // tile fully above diagonal
    int t0 = bx * 128, s0 = by * 128, b = blockIdx.z;

    __shared__ float Ah[2][128][12], Al[2][128][12];   // q  [t][h8]
    __shared__ float Bh[2][8][136],  Bl[2][8][136];    // k^T [h8][s]

    const float* qb = g_q + (size_t)b * TT * HH;
    const float* kb = g_k + (size_t)b * TT * HH;

    int tid = threadIdx.x;
    int warp = tid >> 5, lane = tid & 31, g = lane >> 2, tq = lane & 3;
    int mbase = (warp >> 1) * 32, nbase = (warp & 1) * 64;
    int ra = tid >> 1, ca = (tid & 1) * 4;

    float acc[2][8][4];
#pragma unroll
    for (int i = 0; i < 2; i++)
#pragma unroll
        for (int j = 0; j < 8; j++)
#pragma unroll
            for (int q = 0; q < 4; q++) acc[i][j][q] = 0.f;

    float4 sA, sB;
    auto LOAD = [&](int h0) {
        sA = *(const float4*)&qb[(size_t)(t0 + ra) * HH + h0 + ca];
        sB = *(const float4*)&kb[(size_t)(s0 + ra) * HH + h0 + ca];
    };
    auto STORE = [&](int bsel) {
        float4 h = cvt4(sA);
        *(float4*)&Ah[bsel][ra][ca] = h;
        *(float4*)&Al[bsel][ra][ca] = sub4(sA, h);
        float vv[4] = {sB.x, sB.y, sB.z, sB.w};
#pragma unroll
        for (int j = 0; j < 4; j++) {
            float hb = tf32_rna(vv[j]);
            Bh[bsel][ca + j][ra] = hb;
            Bl[bsel][ca + j][ra] = vv[j] - hb;
        }
    };
    auto COMPUTE = [&](int bsel) {
        unsigned ah[2][4], al[2][4];
#pragma unroll
        for (int ma = 0; ma < 2; ma++) {
            int r0 = mbase + ma * 16 + g;
            ah[ma][0] = fau(Ah[bsel][r0][tq]);     ah[ma][1] = fau(Ah[bsel][r0 + 8][tq]);
            ah[ma][2] = fau(Ah[bsel][r0][tq + 4]); ah[ma][3] = fau(Ah[bsel][r0 + 8][tq + 4]);
            al[ma][0] = fau(Al[bsel][r0][tq]);     al[ma][1] = fau(Al[bsel][r0 + 8][tq]);
            al[ma][2] = fau(Al[bsel][r0][tq + 4]); al[ma][3] = fau(Al[bsel][r0 + 8][tq + 4]);
        }
#pragma unroll
        for (int nb = 0; nb < 8; nb++) {
            int cc = nbase + nb * 8 + g;
            unsigned bh[2], bl[2];
            bh[0] = fau(Bh[bsel][tq][cc]); bh[1] = fau(Bh[bsel][tq + 4][cc]);
            bl[0] = fau(Bl[bsel][tq][cc]); bl[1] = fau(Bl[bsel][tq + 4][cc]);
#pragma unroll
            for (int ma = 0; ma < 2; ma++) {
                mma8(acc[ma][nb], ah[ma], bh);
                mma8(acc[ma][nb], ah[ma], bl);
                mma8(acc[ma][nb], al[ma], bh);
            }
        }
    };

    LOAD(0); STORE(0); __syncthreads();
    const int NC = HH / 8;
    for (int c = 0; c < NC; c++) {
        if (c + 1 < NC) LOAD((c + 1) * 8);
        COMPUTE(c & 1);
        if (c + 1 < NC) STORE((c + 1) & 1);
        __syncthreads();
    }

    float* Sb = g_S + (size_t)b * TT * TT;
    const float scale = 11.31370849898476f;   // sqrt(128)
#pragma unroll
    for (int ma = 0; ma < 2; ma++)
#pragma unroll
        for (int nb = 0; nb < 8; nb++) {
            int r0 = t0 + mbase + ma * 16 + g;
            int cc = s0 + nbase + nb * 8 + 2 * tq;
            *(float2*)&Sb[(size_t)r0 * TT + cc] =
                make_float2(acc[ma][nb][0] * scale, acc[ma][nb][1] * scale);
            *(float2*)&Sb[(size_t)(r0 + 8) * TT + cc] =
                make_float2(acc[ma][nb][2] * scale, acc[ma][nb][3] * scale);
        }

    // fused per-column max over this tile (mask above-diagonal on diag tiles)
    bool diag = (bx == by);
#pragma unroll
    for (int nb = 0; nb < 8; nb++) {
#pragma unroll
        for (int p = 0; p < 2; p++) {
            int scol = nbase + nb * 8 + 2 * tq + p;   // local col in tile
            float m = -INFINITY;
#pragma unroll
            for (int ma = 0; ma < 2; ma++) {
#pragma unroll
                for (int rp = 0; rp < 2; rp++) {
                    int rrow = mbase + ma * 16 + g + rp * 8;
                    float v = acc[ma][nb][rp * 2 + p] * scale;
                    if (!diag || rrow >= scol) m = fmaxf(m, v);
                }
            }
            m = fmaxf(m, __shfl_xor_sync(0xffffffffu, m, 4));
            m = fmaxf(m, __shfl_xor_sync(0xffffffffu, m, 8));
            m = fmaxf(m, __shfl_xor_sync(0xffffffffu, m, 16));
            if (g == 0)
                atomicMax(&g_cmaxu[(size_t)b * TT + s0 + scol], fenc(m));
        }
    }
}

// -------- pass B: E = exp(S - cmax) in place + partial column sums ---------
__global__ void expsum_partial() {
    int col = blockIdx.x * 256 + threadIdx.x;
    int b = col >> 11, s = col & 2047;
    int t0c = blockIdx.y * 256, t1c = t0c + 256;
    float* Sb = g_S + (size_t)b * TT * TT;
    const float L = 1.4426950408889634f;
    float cml = fdec(g_cmaxu[col]) * L;

    // zero the garbage region above the diagonal inside this column's 128-block
    int z0 = s & ~127; if (z0 < t0c) z0 = t0c;
    int z1 = (s < t1c) ? s : t1c;
    for (int t = z0; t < z1; t++) Sb[(size_t)t * TT + s] = 0.f;

    float d0 = 0.f, d1 = 0.f, d2 = 0.f, d3 = 0.f;
    int t = (s > t0c) ? s : t0c;
    for (; t + 3 < t1c; t += 4) {
        float v0 = Sb[(size_t)t * TT + s];
        float v1 = Sb[(size_t)(t + 1) * TT + s];
        float v2 = Sb[(size_t)(t + 2) * TT + s];
        float v3 = Sb[(size_t)(t + 3) * TT + s];
        float e0 = ex2f(fmaf(v0, L, -cml));
        float e1 = ex2f(fmaf(v1, L, -cml));
        float e2 = ex2f(fmaf(v2, L, -cml));
        float e3 = ex2f(fmaf(v3, L, -cml));
        Sb[(size_t)t * TT + s]       = e0;
        Sb[(size_t)(t + 1) * TT + s] = e1;
        Sb[(size_t)(t + 2) * TT + s] = e2;
        Sb[(size_t)(t + 3) * TT + s] = e3;
        d0 += e0; d1 += e1; d2 += e2; d3 += e3;
    }
    for (; t < t1c; t++) {
        float e = ex2f(fmaf(Sb[(size_t)t * TT + s], L, -cml));
        Sb[(size_t)t * TT + s] = e;
        d0 += e;
    }
    g_psum[blockIdx.y * BT + col] = (d0 + d1) + (d2 + d3);
}

__global__ void den_combine() {
    int col = blockIdx.x * 256 + threadIdx.x;
    float d = 0.f;
#pragma unroll
    for (int c = 0; c < 8; c++) d += g_psum[c * BT + col];
    g_crcp[col] = 1.f / d;
}

// ---------------- K4: out = E @ (v * crcp)  (1xTF32, pipelined) ------------
__global__ void __launch_bounds__(256) out_kernel(float* __restrict__ outp) {
    int t0 = blockIdx.x * 128;
    int b  = blockIdx.y;

    __shared__ float Ah[2][128][12];    // E tile  [t][s8]
    __shared__ float Bh[2][8][136];     // v' tile [s8][h]

    const float* Sb = g_S + (size_t)b * TT * TT;
    const float* vb = g_v + (size_t)b * TT * HH;
    const float* crcp = g_crcp + b * TT;

    int tid = threadIdx.x;
    int warp = tid >> 5, lane = tid & 31, g = lane >> 2, tq = lane & 3;
    int mbase = (warp >> 1) * 32, nbase = (warp & 1) * 64;
    int ra = tid >> 1, ca = (tid & 1) * 4;
    int rb = tid >> 5, cb = (tid & 31) * 4;

    float acc[2][8][4];
#pragma unroll
    for (int i = 0; i < 2; i++)
#pragma unroll
        for (int j = 0; j < 8; j++)
#pragma unroll
            for (int q = 0; q < 4; q++) acc[i][j][q] = 0.f;

    float4 sA, sB; float sC;
    auto LOAD = [&](int s0c) {
        sA = *(const float4*)&Sb[(size_t)(t0 + ra) * TT + s0c + ca];
        sB = *(const float4*)&vb[(size_t)(s0c + rb) * HH + cb];
        sC = crcp[s0c + rb];
    };
    auto STORE = [&](int bsel) {
        *(float4*)&Ah[bsel][ra][ca] = cvt4(sA);
        float4 vsc = make_float4(sB.x * sC, sB.y * sC, sB.z * sC, sB.w * sC);
        *(float4*)&Bh[bsel][rb][cb] = cvt4(vsc);
    };
    auto COMPUTE = [&](int bsel) {
        unsigned ah[2][4];
#pragma unroll
        for (int ma = 0; ma < 2; ma++) {
            int r0 = mbase + ma * 16 + g;
            ah[ma][0] = fau(Ah[bsel][r0][tq]);     ah[ma][1] = fau(Ah[bsel][r0 + 8][tq]);
            ah[ma][2] = fau(Ah[bsel][r0][tq + 4]); ah[ma][3] = fau(Ah[bsel][r0 + 8][tq + 4]);
        }
#pragma unroll
        for (int nb = 0; nb < 8; nb++) {
            int cc = nbase + nb * 8 + g;
            unsigned bh[2];
            bh[0] = fau(Bh[bsel][tq][cc]); bh[1] = fau(Bh[bsel][tq + 4][cc]);
#pragma unroll
            for (int ma = 0; ma < 2; ma++) mma8(acc[ma][nb], ah[ma], bh);
        }
    };

    LOAD(0); STORE(0); __syncthreads();
    const int NC = t0 / 8 + 16;          // s <= t0+127
    for (int c = 0; c < NC; c++) {
        if (c + 1 < NC) LOAD((c + 1) * 8);
        COMPUTE(c & 1);
        if (c + 1 < NC) STORE((c + 1) & 1);
        __syncthreads();
    }

#pragma unroll
    for (int ma = 0; ma < 2; ma++)
#pragma unroll
        for (int nb = 0; nb < 8; nb++) {
            int r0 = t0 + mbase + ma * 16 + g;
            int cc = nbase + nb * 8 + 2 * tq;
            *(float2*)&outp[((size_t)b * TT + r0) * HH + cc] =
                make_float2(acc[ma][nb][0], acc[ma][nb][1]);
            *(float2*)&outp[((size_t)b * TT + r0 + 8) * HH + cc] =
                make_float2(acc[ma][nb][2], acc[ma][nb][3]);
        }
}

// ---------------------------------------------------------------------------
extern "C" void kernel_launch(void* const* d_in, const int* in_sizes, int n_in,
                              void* d_out, int out_size) {
    const float* x  = (const float*)d_in[0];
    const float* Wk = (const float*)d_in[1];
    const float* Wq = (const float*)d_in[2];
    const float* Wv = (const float*)d_in[3];
    float* out = (float*)d_out;

    init_cmax<<<BT / 256, 256>>>();
    qkv_kernel<<<dim3(BT / 128, 3), 256>>>(x, Wk, Wq, Wv);
    score_kernel<<<dim3(TT / 128, TT / 128, BB), 256>>>();
    expsum_partial<<<dim3(BT / 256, 8), 256>>>();
    den_combine<<<BT / 256, 256>>>();
    out_kernel<<<dim3(TT / 128, BB), 256>>>(out);
}

// round 10
// speedup vs baseline: 1.5944x; 1.2772x over previous
#include <cuda_runtime.h>
#include <math.h>

#define BB 8
#define TT 2048
#define EE 1024
#define HH 128
#define BT (BB*TT)

// ---------------- scratch (device globals: allocation-free) ----------------
__device__ float g_k[BT*HH];
__device__ float g_q[BT*HH];
__device__ float g_v[BT*HH];
__device__ float g_S[(size_t)BB*TT*TT];   // S, then overwritten with E=exp(S-cmax)
__device__ float g_psum[8*BT];
__device__ unsigned g_cmaxu[BT];          // encoded column max (atomicMax)
__device__ float g_crcp[BT];              // 1/den

// ---------------- helpers --------------------------------------------------
__device__ __forceinline__ float tf32_rna(float x) {
    unsigned u;
    asm("cvt.rna.tf32.f32 %0, %1;" : "=r"(u) : "f"(x));
    return __uint_as_float(u);
}
__device__ __forceinline__ unsigned fau(float x) { return __float_as_uint(x); }

// monotone float<->unsigned encoding for atomicMax
__device__ __forceinline__ unsigned fenc(float f) {
    unsigned u = __float_as_uint(f);
    return (u & 0x80000000u) ? ~u : (u | 0x80000000u);
}
__device__ __forceinline__ float fdec(unsigned e) {
    unsigned u = (e & 0x80000000u) ? (e & 0x7fffffffu) : ~e;
    return __uint_as_float(u);
}

__device__ __forceinline__ void mma8(float c[4], const unsigned a[4], const unsigned b[2]) {
    asm volatile(
        "mma.sync.aligned.m16n8k8.row.col.f32.tf32.tf32.f32 "
        "{%0,%1,%2,%3}, {%4,%5,%6,%7}, {%8,%9}, {%0,%1,%2,%3};\n"
        : "+f"(c[0]), "+f"(c[1]), "+f"(c[2]), "+f"(c[3])
        : "r"(a[0]), "r"(a[1]), "r"(a[2]), "r"(a[3]), "r"(b[0]), "r"(b[1]));
}
__device__ __forceinline__ float ex2f(float y) {
    float e;
    asm("ex2.approx.f32 %0, %1;" : "=f"(e) : "f"(y));
    return e;
}
__device__ __forceinline__ void cp16(void* dst, const void* src) {
    unsigned d = (unsigned)__cvta_generic_to_shared(dst);
    asm volatile("cp.async.cg.shared.global [%0], [%1], 16;" :: "r"(d), "l"(src));
}
#define CP_COMMIT() asm volatile("cp.async.commit_group;")
#define CP_WAIT2()  asm volatile("cp.async.wait_group 2;")

// split one raw value into tf32 hi/lo register pair
#define SPLIT(raw, hi, lo) { float _h = tf32_rna(raw); hi = fau(_h); lo = fau((raw) - _h); }

// ---------------- init: cmax accumulators to encoded -inf ------------------
__global__ void init_cmax() {
    g_cmaxu[blockIdx.x * 256 + threadIdx.x] = 0x007fffffu;  // fenc(-inf)
}

// ---------------- K1: q/k/v = x @ W  (3xTF32, cp.async 4-stage) ------------
__global__ void __launch_bounds__(256) qkv_kernel(const float* __restrict__ x,
                                                  const float* __restrict__ Wk,
                                                  const float* __restrict__ Wq,
                                                  const float* __restrict__ Wv) {
    const float* W    = (blockIdx.y == 0) ? Wk : (blockIdx.y == 1) ? Wq : Wv;
    float*       outp = (blockIdx.y == 0) ? g_k : (blockIdx.y == 1) ? g_q : g_v;

    __shared__ float As[4][128][12];   // x raw   [m][k8]
    __shared__ float Bs[4][8][136];    // W raw   [k8][n]

    int tid = threadIdx.x;
    int m0 = blockIdx.x * 128;
    int warp = tid >> 5, lane = tid & 31, g = lane >> 2, tq = lane & 3;
    int mbase = (warp >> 1) * 32, nbase = (warp & 1) * 64;
    int ra = tid >> 1, ca = (tid & 1) * 4;
    int rb = tid >> 5, cb = (tid & 31) * 4;

    float acc[2][8][4];
#pragma unroll
    for (int i = 0; i < 2; i++)
#pragma unroll
        for (int j = 0; j < 8; j++)
#pragma unroll
            for (int q = 0; q < 4; q++) acc[i][j][q] = 0.f;

    const int NC = EE / 8;
    auto ISSUE = [&](int c) {
        int st = c & 3, k0 = c * 8;
        cp16(&As[st][ra][ca], &x[(size_t)(m0 + ra) * EE + k0 + ca]);
        cp16(&Bs[st][rb][cb], &W[(size_t)(k0 + rb) * HH + cb]);
        CP_COMMIT();
    };
    auto COMPUTE = [&](int st) {
        unsigned ah[2][4], al[2][4];
#pragma unroll
        for (int ma = 0; ma < 2; ma++) {
            int r0 = mbase + ma * 16 + g;
            SPLIT(As[st][r0][tq],         ah[ma][0], al[ma][0]);
            SPLIT(As[st][r0 + 8][tq],     ah[ma][1], al[ma][1]);
            SPLIT(As[st][r0][tq + 4],     ah[ma][2], al[ma][2]);
            SPLIT(As[st][r0 + 8][tq + 4], ah[ma][3], al[ma][3]);
        }
#pragma unroll
        for (int nb = 0; nb < 8; nb++) {
            int cc = nbase + nb * 8 + g;
            unsigned bh[2], bl[2];
            SPLIT(Bs[st][tq][cc],     bh[0], bl[0]);
            SPLIT(Bs[st][tq + 4][cc], bh[1], bl[1]);
#pragma unroll
            for (int ma = 0; ma < 2; ma++) {
                mma8(acc[ma][nb], ah[ma], bh);
                mma8(acc[ma][nb], ah[ma], bl);
                mma8(acc[ma][nb], al[ma], bh);
            }
        }
    };

    ISSUE(0); ISSUE(1); ISSUE(2);
    for (int c = 0; c < NC; c++) {
        CP_WAIT2();
        __syncthreads();
        if (c + 3 < NC) ISSUE(c + 3); else CP_COMMIT();
        COMPUTE(c & 3);
    }

#pragma unroll
    for (int ma = 0; ma < 2; ma++)
#pragma unroll
        for (int nb = 0; nb < 8; nb++) {
            int r0 = m0 + mbase + ma * 16 + g;
            int cc = nbase + nb * 8 + 2 * tq;
            *(float2*)&outp[(size_t)r0 * HH + cc]       = make_float2(acc[ma][nb][0], acc[ma][nb][1]);
            *(float2*)&outp[(size_t)(r0 + 8) * HH + cc] = make_float2(acc[ma][nb][2], acc[ma][nb][3]);
        }
}

// ---------------- K2: S = sqrt(H)*q@k^T + fused colmax (cp.async) ----------
__global__ void __launch_bounds__(256) score_kernel() {
    int bx = blockIdx.x, by = blockIdx.y;
    if (bx < by) return;                      // tile fully above diagonal
    int t0 = bx * 128, s0 = by * 128, b = blockIdx.z;

    __shared__ float As[4][128][12];   // q raw  [t][h8]
    __shared__ float Bs[4][128][12];   // k raw  [s][h8] (row-major; transposed on read)

    const float* qb = g_q + (size_t)b * TT * HH;
    const float* kb = g_k + (size_t)b * TT * HH;

    int tid = threadIdx.x;
    int warp = tid >> 5, lane = tid & 31, g = lane >> 2, tq = lane & 3;
    int mbase = (warp >> 1) * 32, nbase = (warp & 1) * 64;
    int ra = tid >> 1, ca = (tid & 1) * 4;

    float acc[2][8][4];
#pragma unroll
    for (int i = 0; i < 2; i++)
#pragma unroll
        for (int j = 0; j < 8; j++)
#pragma unroll
            for (int q = 0; q < 4; q++) acc[i][j][q] = 0.f;

    const int NC = HH / 8;
    auto ISSUE = [&](int c) {
        int st = c & 3, h0 = c * 8;
        cp16(&As[st][ra][ca], &qb[(size_t)(t0 + ra) * HH + h0 + ca]);
        cp16(&Bs[st][ra][ca], &kb[(size_t)(s0 + ra) * HH + h0 + ca]);
        CP_COMMIT();
    };
    auto COMPUTE = [&](int st) {
        unsigned ah[2][4], al[2][4];
#pragma unroll
        for (int ma = 0; ma < 2; ma++) {
            int r0 = mbase + ma * 16 + g;
            SPLIT(As[st][r0][tq],         ah[ma][0], al[ma][0]);
            SPLIT(As[st][r0 + 8][tq],     ah[ma][1], al[ma][1]);
            SPLIT(As[st][r0][tq + 4],     ah[ma][2], al[ma][2]);
            SPLIT(As[st][r0 + 8][tq + 4], ah[ma][3], al[ma][3]);
        }
#pragma unroll
        for (int nb = 0; nb < 8; nb++) {
            int cc = nbase + nb * 8 + g;   // n index = k row
            unsigned bh[2], bl[2];
            SPLIT(Bs[st][cc][tq],     bh[0], bl[0]);
            SPLIT(Bs[st][cc][tq + 4], bh[1], bl[1]);
#pragma unroll
            for (int ma = 0; ma < 2; ma++) {
                mma8(acc[ma][nb], ah[ma], bh);
                mma8(acc[ma][nb], ah[ma], bl);
                mma8(acc[ma][nb], al[ma], bh);
            }
        }
    };

    ISSUE(0); ISSUE(1); ISSUE(2);
    for (int c = 0; c < NC; c++) {
        CP_WAIT2();
        __syncthreads();
        if (c + 3 < NC) ISSUE(c + 3); else CP_COMMIT();
        COMPUTE(c & 3);
    }

    float* Sb = g_S + (size_t)b * TT * TT;
    const float scale = 11.31370849898476f;   // sqrt(128)
#pragma unroll
    for (int ma = 0; ma < 2; ma++)
#pragma unroll
        for (int nb = 0; nb < 8; nb++) {
            int r0 = t0 + mbase + ma * 16 + g;
            int cc = s0 + nbase + nb * 8 + 2 * tq;
            *(float2*)&Sb[(size_t)r0 * TT + cc] =
                make_float2(acc[ma][nb][0] * scale, acc[ma][nb][1] * scale);
            *(float2*)&Sb[(size_t)(r0 + 8) * TT + cc] =
                make_float2(acc[ma][nb][2] * scale, acc[ma][nb][3] * scale);
        }

    // fused per-column max over this tile (mask above-diagonal on diag tiles)
    bool diag = (bx == by);
#pragma unroll
    for (int nb = 0; nb < 8; nb++) {
#pragma unroll
        for (int p = 0; p < 2; p++) {
            int scol = nbase + nb * 8 + 2 * tq + p;   // local col in tile
            float m = -INFINITY;
#pragma unroll
            for (int ma = 0; ma < 2; ma++) {
#pragma unroll
                for (int rp = 0; rp < 2; rp++) {
                    int rrow = mbase + ma * 16 + g + rp * 8;
                    float v = acc[ma][nb][rp * 2 + p] * scale;
                    if (!diag || rrow >= scol) m = fmaxf(m, v);
                }
            }
            m = fmaxf(m, __shfl_xor_sync(0xffffffffu, m, 4));
            m = fmaxf(m, __shfl_xor_sync(0xffffffffu, m, 8));
            m = fmaxf(m, __shfl_xor_sync(0xffffffffu, m, 16));
            if (g == 0)
                atomicMax(&g_cmaxu[(size_t)b * TT + s0 + scol], fenc(m));
        }
    }
}

// -------- pass B: E = exp(S - cmax) in place + partial column sums ---------
__global__ void expsum_partial() {
    int col = blockIdx.x * 256 + threadIdx.x;
    int b = col >> 11, s = col & 2047;
    int t0c = blockIdx.y * 256, t1c = t0c + 256;
    float* Sb = g_S + (size_t)b * TT * TT;
    const float L = 1.4426950408889634f;
    float cml = fdec(g_cmaxu[col]) * L;

    // zero the garbage region above the diagonal inside this column's 128-block
    int z0 = s & ~127; if (z0 < t0c) z0 = t0c;
    int z1 = (s < t1c) ? s : t1c;
    for (int t = z0; t < z1; t++) Sb[(size_t)t * TT + s] = 0.f;

    float d0 = 0.f, d1 = 0.f, d2 = 0.f, d3 = 0.f;
    int t = (s > t0c) ? s : t0c;
    for (; t + 3 < t1c; t += 4) {
        float v0 = Sb[(size_t)t * TT + s];
        float v1 = Sb[(size_t)(t + 1) * TT + s];
        float v2 = Sb[(size_t)(t + 2) * TT + s];
        float v3 = Sb[(size_t)(t + 3) * TT + s];
        float e0 = ex2f(fmaf(v0, L, -cml));
        float e1 = ex2f(fmaf(v1, L, -cml));
        float e2 = ex2f(fmaf(v2, L, -cml));
        float e3 = ex2f(fmaf(v3, L, -cml));
        Sb[(size_t)t * TT + s]       = e0;
        Sb[(size_t)(t + 1) * TT + s] = e1;
        Sb[(size_t)(t + 2) * TT + s] = e2;
        Sb[(size_t)(t + 3) * TT + s] = e3;
        d0 += e0; d1 += e1; d2 += e2; d3 += e3;
    }
    for (; t < t1c; t++) {
        float e = ex2f(fmaf(Sb[(size_t)t * TT + s], L, -cml));
        Sb[(size_t)t * TT + s] = e;
        d0 += e;
    }
    g_psum[blockIdx.y * BT + col] = (d0 + d1) + (d2 + d3);
}

__global__ void den_combine() {
    int col = blockIdx.x * 256 + threadIdx.x;
    float d = 0.f;
#pragma unroll
    for (int c = 0; c < 8; c++) d += g_psum[c * BT + col];
    g_crcp[col] = 1.f / d;
}

// -------- scale V rows by 1/den (g_v recomputed each launch: replay-safe) --
__global__ void scale_v() {
    int idx = blockIdx.x * 256 + threadIdx.x;      // float4 index
    int row = idx >> 5;                            // HH/4 = 32 float4 per row
    float c = g_crcp[row];
    float4* p = (float4*)g_v + idx;
    float4 v = *p;
    *p = make_float4(v.x * c, v.y * c, v.z * c, v.w * c);
}

// ---------------- K4: out = E @ v'  (1xTF32, cp.async 4-stage) -------------
__global__ void __launch_bounds__(256) out_kernel(float* __restrict__ outp) {
    int t0 = blockIdx.x * 128;
    int b  = blockIdx.y;

    __shared__ float As[4][128][12];    // E raw  [t][s8]
    __shared__ float Bs[4][8][136];     // v' raw [s8][h]

    const float* Sb = g_S + (size_t)b * TT * TT;
    const float* vb = g_v + (size_t)b * TT * HH;

    int tid = threadIdx.x;
    int warp = tid >> 5, lane = tid & 31, g = lane >> 2, tq = lane & 3;
    int mbase = (warp >> 1) * 32, nbase = (warp & 1) * 64;
    int ra = tid >> 1, ca = (tid & 1) * 4;
    int rb = tid >> 5, cb = (tid & 31) * 4;

    float acc[2][8][4];
#pragma unroll
    for (int i = 0; i < 2; i++)
#pragma unroll
        for (int j = 0; j < 8; j++)
#pragma unroll
            for (int q = 0; q < 4; q++) acc[i][j][q] = 0.f;

    const int NC = t0 / 8 + 16;          // s <= t0+127
    auto ISSUE = [&](int c) {
        int st = c & 3, s0c = c * 8;
        cp16(&As[st][ra][ca], &Sb[(size_t)(t0 + ra) * TT + s0c + ca]);
        cp16(&Bs[st][rb][cb], &vb[(size_t)(s0c + rb) * HH + cb]);
        CP_COMMIT();
    };
    auto COMPUTE = [&](int st) {
        unsigned ah[2][4];
#pragma unroll
        for (int ma = 0; ma < 2; ma++) {
            int r0 = mbase + ma * 16 + g;
            ah[ma][0] = fau(tf32_rna(As[st][r0][tq]));
            ah[ma][1] = fau(tf32_rna(As[st][r0 + 8][tq]));
            ah[ma][2] = fau(tf32_rna(As[st][r0][tq + 4]));
            ah[ma][3] = fau(tf32_rna(As[st][r0 + 8][tq + 4]));
        }
#pragma unroll
        for (int nb = 0; nb < 8; nb++) {
            int cc = nbase + nb * 8 + g;
            unsigned bh[2];
            bh[0] = fau(tf32_rna(Bs[st][tq][cc]));
            bh[1] = fau(tf32_rna(Bs[st][tq + 4][cc]));
#pragma unroll
            for (int ma = 0; ma < 2; ma++) mma8(acc[ma][nb], ah[ma], bh);
        }
    };

    ISSUE(0); ISSUE(1); ISSUE(2);
    for (int c = 0; c < NC; c++) {
        CP_WAIT2();
        __syncthreads();
        if (c + 3 < NC) ISSUE(c + 3); else CP_COMMIT();
        COMPUTE(c & 3);
    }

#pragma unroll
    for (int ma = 0; ma < 2; ma++)
#pragma unroll
        for (int nb = 0; nb < 8; nb++) {
            int r0 = t0 + mbase + ma * 16 + g;
            int cc = nbase + nb * 8 + 2 * tq;
            *(float2*)&outp[((size_t)b * TT + r0) * HH + cc] =
                make_float2(acc[ma][nb][0], acc[ma][nb][1]);
            *(float2*)&outp[((size_t)b * TT + r0 + 8) * HH + cc] =
                make_float2(acc[ma][nb][2], acc[ma][nb][3]);
        }
}

// ---------------------------------------------------------------------------
extern "C" void kernel_launch(void* const* d_in, const int* in_sizes, int n_in,
                              void* d_out, int out_size) {
    const float* x  = (const float*)d_in[0];
    const float* Wk = (const float*)d_in[1];
    const float* Wq = (const float*)d_in[2];
    const float* Wv = (const float*)d_in[3];
    float* out = (float*)d_out;

    init_cmax<<<BT / 256, 256>>>();
    qkv_kernel<<<dim3(BT / 128, 3), 256>>>(x, Wk, Wq, Wv);
    score_kernel<<<dim3(TT / 128, TT / 128, BB), 256>>>();
    expsum_partial<<<dim3(BT / 256, 8), 256>>>();
    den_combine<<<BT / 256, 256>>>();
    scale_v<<<(BT * HH / 4) / 256, 256>>>();
    out_kernel<<<dim3(TT / 128, BB), 256>>>(out);
}